// round 9
// baseline (speedup 1.0000x reference)
#include <cuda_runtime.h>
#include <cuda_bf16.h>
#include <math_constants.h>

// Problem constants (shapes fixed by the dataset)
#define NODES_MAX 100000
#define EDGES_MAX 1600000
#define IN_DIM    256
#define HEADS     4
#define OUT_DIM   32
#define HD        128          // HEADS*OUT_DIM
#define NEG_SLOPE 0.2f

// ---------------- static scratch (no allocations allowed) ----------------
__device__ float g_feat[(size_t)NODES_MAX * HD];   // [N,128] fp32
__device__ float g_el[NODES_MAX * HEADS];          // [N,4]
__device__ float g_er[NODES_MAX * HEADS];          // [N,4]
__device__ int   g_deg[NODES_MAX];
__device__ int   g_off[NODES_MAX];
__device__ int   g_cursor[NODES_MAX];
__device__ int   g_bsums[256];
__device__ int   g_csr_src[EDGES_MAX];
__device__ float4 g_w[EDGES_MAX];                  // per-edge unnormalized softmax weights
__device__ __nv_bfloat16 g_Wt_hi[HD * IN_DIM];     // W^T split: [n][k]
__device__ __nv_bfloat16 g_Wt_lo[HD * IN_DIM];

__device__ __forceinline__ float leaky(float x) {
    return x > 0.0f ? x : NEG_SLOPE * x;
}

__device__ __forceinline__ void split_bf16(float v, __nv_bfloat16& hi, __nv_bfloat16& lo) {
    hi = __float2bfloat16(v);
    lo = __float2bfloat16(v - __bfloat162float(hi));
}

__device__ __forceinline__ unsigned cvta_smem(const void* p) {
    unsigned a;
    asm("{ .reg .u64 t; cvta.to.shared.u64 t, %1; cvt.u32.u64 %0, t; }" : "=r"(a) : "l"(p));
    return a;
}
__device__ __forceinline__ void cp16(unsigned dst, const void* src) {
    asm volatile("cp.async.cg.shared.global [%0], [%1], 16;\n" :: "r"(dst), "l"(src));
}
__device__ __forceinline__ void cp_commit() { asm volatile("cp.async.commit_group;\n"); }
__device__ __forceinline__ void cp_wait_all() { asm volatile("cp.async.wait_group 0;\n"); }

// ---------------- 0. W -> transposed bf16 hi/lo split + zero degrees ----------------
__global__ void wconv_zero_kernel(const float* __restrict__ W, int N) {
    int idx = blockIdx.x * blockDim.x + threadIdx.x;
    if (idx < N) g_deg[idx] = 0;
    if (idx >= IN_DIM * HD) return;
    int k = idx >> 7;        // 0..255
    int n = idx & 127;       // 0..127
    __nv_bfloat16 hi, lo;
    split_bf16(W[idx], hi, lo);
    g_Wt_hi[n * IN_DIM + k] = hi;
    g_Wt_lo[n * IN_DIM + k] = lo;
}

// ---------------- 1. Tensor-core GEMM: feat = x @ W (+ fused el/er) ----------------
// BM=128, BN=128, BK=32, 256 threads = 8 warps; warp tile 64x32 (warp cols = one head).
// Double-buffered smem, cp.async for B, register-staged A, ONE sync per chunk.
// Error-compensated: acc += Ahi*Bhi + Ahi*Blo + Alo*Bhi  (fp32 accumulate)
__device__ __forceinline__ void mma16816(float* d, const unsigned* a, const unsigned* b) {
    asm volatile(
        "mma.sync.aligned.m16n8k16.row.col.f32.bf16.bf16.f32 "
        "{%0,%1,%2,%3}, {%4,%5,%6,%7}, {%8,%9}, {%0,%1,%2,%3};\n"
        : "+f"(d[0]), "+f"(d[1]), "+f"(d[2]), "+f"(d[3])
        : "r"(a[0]), "r"(a[1]), "r"(a[2]), "r"(a[3]), "r"(b[0]), "r"(b[1]));
}

#define BK     32
#define ASTR   40                    // bf16 per padded row (80B) -> conflict-free
#define TILE_E (128 * ASTR)          // 5120 bf16 per tile
#define NCH    (IN_DIM / BK)         // 8
// dynamic smem layout (bf16 elems): AHI[2] ALO[2] BHI[2] BLO[2]
#define SM_AHI(p) ((p) * TILE_E)
#define SM_ALO(p) (2 * TILE_E + (p) * TILE_E)
#define SM_BHI(p) (4 * TILE_E + (p) * TILE_E)
#define SM_BLO(p) (6 * TILE_E + (p) * TILE_E)
#define SMEM_BYTES (8 * TILE_E * 2)  // 81920

__global__ void __launch_bounds__(256, 2)
gemm_tc_kernel(const float* __restrict__ A,
               const float* __restrict__ attn_l,
               const float* __restrict__ attn_r, int M) {
    extern __shared__ __align__(16) __nv_bfloat16 sm[];

    const int tid  = threadIdx.x;
    const int wid  = tid >> 5;
    const int lane = tid & 31;
    const int brow = blockIdx.x * 128;

    const int warp_m = (wid & 1) * 64;    // 4 m-tiles of 16
    const int warp_n = (wid >> 1) * 32;   // head = wid>>1

    float acc[4][4][4];
#pragma unroll
    for (int i = 0; i < 4; i++)
#pragma unroll
        for (int j = 0; j < 4; j++)
#pragma unroll
            for (int c = 0; c < 4; c++) acc[i][j][c] = 0.0f;

    const int r  = lane >> 2;         // 0..7
    const int kq = (lane & 3) * 2;    // 0,2,4,6

    // A staging registers (one 128x32 tile spread over 256 threads x 4 float4)
    float4 rA[4];
    const int aRow = tid >> 1;                   // each linear i: row = (tid+256i)>>3
    (void)aRow;

    auto ldA = [&](int chunk) {
        const int k0 = chunk * BK;
#pragma unroll
        for (int i = 0; i < 4; i++) {
            int linear = tid + 256 * i;          // 0..1023
            int row = linear >> 3;               // 0..127
            int col = (linear & 7) * 4;          // 0..28
            rA[i] = make_float4(0.f, 0.f, 0.f, 0.f);
            if (brow + row < M)
                rA[i] = *reinterpret_cast<const float4*>(A + (size_t)(brow + row) * IN_DIM + k0 + col);
        }
    };
    auto stsA = [&](int buf) {
#pragma unroll
        for (int i = 0; i < 4; i++) {
            int linear = tid + 256 * i;
            int row = linear >> 3;
            int col = (linear & 7) * 4;
            __nv_bfloat16 h0, l0, h1, l1, h2, l2, h3, l3;
            split_bf16(rA[i].x, h0, l0); split_bf16(rA[i].y, h1, l1);
            split_bf16(rA[i].z, h2, l2); split_bf16(rA[i].w, h3, l3);
            __nv_bfloat16* ph = sm + SM_AHI(buf) + row * ASTR + col;
            __nv_bfloat16* pl = sm + SM_ALO(buf) + row * ASTR + col;
            ph[0] = h0; ph[1] = h1; ph[2] = h2; ph[3] = h3;
            pl[0] = l0; pl[1] = l1; pl[2] = l2; pl[3] = l3;
        }
    };
    auto cpB = [&](int chunk, int buf) {
        const int k0 = chunk * BK;
        // 512 granules hi + 512 lo; thread does 2 hi + 2 lo
#pragma unroll
        for (int i = 0; i < 2; i++) {
            int g = tid + 256 * i;               // 0..511
            int n  = g >> 2;                     // 0..127
            int kk = (g & 3) * 8;                // elem offset 0,8,16,24
            unsigned dh = cvta_smem(sm + SM_BHI(buf) + n * ASTR + kk);
            unsigned dl = cvta_smem(sm + SM_BLO(buf) + n * ASTR + kk);
            cp16(dh, &g_Wt_hi[n * IN_DIM + k0 + kk]);
            cp16(dl, &g_Wt_lo[n * IN_DIM + k0 + kk]);
        }
    };

    // ---- prologue: stage chunk 0 ----
    ldA(0);
    cpB(0, 0);
    cp_commit();
    stsA(0);                                     // stalls on LDG once; ok

    for (int chunk = 0; chunk < NCH; chunk++) {
        const int p = chunk & 1;
        cp_wait_all();
        __syncthreads();                         // buf p fully visible to all

        const bool more = (chunk + 1 < NCH);
        if (more) {
            ldA(chunk + 1);                      // LDG issues; data lands during compute
            cpB(chunk + 1, p ^ 1);
            cp_commit();
        }

        const __nv_bfloat16* Ah = sm + SM_AHI(p);
        const __nv_bfloat16* Al = sm + SM_ALO(p);
        const __nv_bfloat16* Bh = sm + SM_BHI(p);
        const __nv_bfloat16* Bl = sm + SM_BLO(p);

#pragma unroll
        for (int ks = 0; ks < 2; ks++) {
            const int kb = ks * 16;
            unsigned bh[4][2], bl[4][2];
#pragma unroll
            for (int nt = 0; nt < 4; nt++) {
                int n = warp_n + nt * 8 + r;
                bh[nt][0] = *reinterpret_cast<const unsigned*>(&Bh[n * ASTR + kb + kq]);
                bh[nt][1] = *reinterpret_cast<const unsigned*>(&Bh[n * ASTR + kb + kq + 8]);
                bl[nt][0] = *reinterpret_cast<const unsigned*>(&Bl[n * ASTR + kb + kq]);
                bl[nt][1] = *reinterpret_cast<const unsigned*>(&Bl[n * ASTR + kb + kq + 8]);
            }
#pragma unroll
            for (int mt = 0; mt < 4; mt++) {
                const int mr = warp_m + mt * 16;
                unsigned ah[4], al[4];
                ah[0] = *reinterpret_cast<const unsigned*>(&Ah[(mr + r) * ASTR + kb + kq]);
                ah[1] = *reinterpret_cast<const unsigned*>(&Ah[(mr + r + 8) * ASTR + kb + kq]);
                ah[2] = *reinterpret_cast<const unsigned*>(&Ah[(mr + r) * ASTR + kb + kq + 8]);
                ah[3] = *reinterpret_cast<const unsigned*>(&Ah[(mr + r + 8) * ASTR + kb + kq + 8]);
                al[0] = *reinterpret_cast<const unsigned*>(&Al[(mr + r) * ASTR + kb + kq]);
                al[1] = *reinterpret_cast<const unsigned*>(&Al[(mr + r + 8) * ASTR + kb + kq]);
                al[2] = *reinterpret_cast<const unsigned*>(&Al[(mr + r) * ASTR + kb + kq + 8]);
                al[3] = *reinterpret_cast<const unsigned*>(&Al[(mr + r + 8) * ASTR + kb + kq + 8]);
#pragma unroll
                for (int nt = 0; nt < 4; nt++) {
                    mma16816(acc[mt][nt], ah, bh[nt]);
                    mma16816(acc[mt][nt], ah, bl[nt]);
                    mma16816(acc[mt][nt], al, bh[nt]);
                }
            }
        }

        if (more) stsA(p ^ 1);   // safe: buf p^1 free since this chunk's barrier
    }

    // ---- epilogue: fp32 store to g_feat + fused el/er (warp-local head dot) ----
    const int cc = (lane & 3) * 2;
    const int head = wid >> 1;

    float alv[8], arv[8];
#pragma unroll
    for (int nt = 0; nt < 4; nt++) {
        int gcol = warp_n + nt * 8 + cc;       // global col = head*32 + local
        alv[nt * 2 + 0] = attn_l[gcol + 0];
        alv[nt * 2 + 1] = attn_l[gcol + 1];
        arv[nt * 2 + 0] = attn_r[gcol + 0];
        arv[nt * 2 + 1] = attn_r[gcol + 1];
    }

#pragma unroll
    for (int mt = 0; mt < 4; mt++) {
        float el_lo = 0.f, el_hi = 0.f, er_lo = 0.f, er_hi = 0.f;
#pragma unroll
        for (int nt = 0; nt < 4; nt++) {
            int grow = brow + warp_m + mt * 16 + r;
            int gcol = warp_n + nt * 8 + cc;
            if (grow < M)
                *reinterpret_cast<float2*>(&g_feat[(size_t)grow * HD + gcol]) =
                    make_float2(acc[mt][nt][0], acc[mt][nt][1]);
            if (grow + 8 < M)
                *reinterpret_cast<float2*>(&g_feat[(size_t)(grow + 8) * HD + gcol]) =
                    make_float2(acc[mt][nt][2], acc[mt][nt][3]);

            el_lo = fmaf(acc[mt][nt][0], alv[nt * 2], fmaf(acc[mt][nt][1], alv[nt * 2 + 1], el_lo));
            er_lo = fmaf(acc[mt][nt][0], arv[nt * 2], fmaf(acc[mt][nt][1], arv[nt * 2 + 1], er_lo));
            el_hi = fmaf(acc[mt][nt][2], alv[nt * 2], fmaf(acc[mt][nt][3], alv[nt * 2 + 1], el_hi));
            er_hi = fmaf(acc[mt][nt][2], arv[nt * 2], fmaf(acc[mt][nt][3], arv[nt * 2 + 1], er_hi));
        }
#pragma unroll
        for (int o = 1; o <= 2; o <<= 1) {
            el_lo += __shfl_xor_sync(0xffffffffu, el_lo, o);
            el_hi += __shfl_xor_sync(0xffffffffu, el_hi, o);
            er_lo += __shfl_xor_sync(0xffffffffu, er_lo, o);
            er_hi += __shfl_xor_sync(0xffffffffu, er_hi, o);
        }
        if ((lane & 3) == 0) {
            int grow = brow + warp_m + mt * 16 + r;
            if (grow < M) {
                g_el[grow * HEADS + head] = el_lo;
                g_er[grow * HEADS + head] = er_lo;
            }
            if (grow + 8 < M) {
                g_el[(grow + 8) * HEADS + head] = el_hi;
                g_er[(grow + 8) * HEADS + head] = er_hi;
            }
        }
    }
}

// ---------------- 2. CSR build ----------------
__global__ void count_kernel(const int* __restrict__ dst, int E) {
    int e4 = (blockIdx.x * blockDim.x + threadIdx.x) * 4;
    if (e4 + 3 < E) {
        int4 d4 = *reinterpret_cast<const int4*>(dst + e4);
        atomicAdd(&g_deg[d4.x], 1);
        atomicAdd(&g_deg[d4.y], 1);
        atomicAdd(&g_deg[d4.z], 1);
        atomicAdd(&g_deg[d4.w], 1);
    } else {
        for (int e = e4; e < E; e++) atomicAdd(&g_deg[dst[e]], 1);
    }
}

__global__ void scan1_kernel(int N) {
    __shared__ int sm1[1024];
    int i = blockIdx.x * 1024 + threadIdx.x;
    int v = (i < N) ? g_deg[i] : 0;
    sm1[threadIdx.x] = v;
    __syncthreads();
    for (int ofs = 1; ofs < 1024; ofs <<= 1) {
        int t = (threadIdx.x >= ofs) ? sm1[threadIdx.x - ofs] : 0;
        __syncthreads();
        sm1[threadIdx.x] += t;
        __syncthreads();
    }
    if (i < N) g_off[i] = sm1[threadIdx.x] - v;       // exclusive
    if (threadIdx.x == 1023) g_bsums[blockIdx.x] = sm1[1023];
}

// parallel block-sum scan (nb <= 128)
__global__ void scan2_kernel(int nb) {
    __shared__ int sm2[128];
    int t = threadIdx.x;
    int v = (t < nb) ? g_bsums[t] : 0;
    sm2[t] = v;
    __syncthreads();
    for (int ofs = 1; ofs < 128; ofs <<= 1) {
        int u = (t >= ofs) ? sm2[t - ofs] : 0;
        __syncthreads();
        sm2[t] += u;
        __syncthreads();
    }
    if (t < nb) g_bsums[t] = sm2[t] - v;              // exclusive
}

__global__ void scan3_kernel(int N) {
    int i = blockIdx.x * blockDim.x + threadIdx.x;
    if (i < N) {
        int o = g_off[i] + g_bsums[i >> 10];
        g_off[i] = o;
        g_cursor[i] = o;
    }
}

__global__ void scatter_kernel(const int* __restrict__ src,
                               const int* __restrict__ dst, int E) {
    int e4 = (blockIdx.x * blockDim.x + threadIdx.x) * 4;
    if (e4 + 3 < E) {
        int4 d4 = *reinterpret_cast<const int4*>(dst + e4);
        int4 s4 = *reinterpret_cast<const int4*>(src + e4);
        g_csr_src[atomicAdd(&g_cursor[d4.x], 1)] = s4.x;
        g_csr_src[atomicAdd(&g_cursor[d4.y], 1)] = s4.y;
        g_csr_src[atomicAdd(&g_cursor[d4.z], 1)] = s4.z;
        g_csr_src[atomicAdd(&g_cursor[d4.w], 1)] = s4.w;
    } else {
        for (int e = e4; e < E; e++)
            g_csr_src[atomicAdd(&g_cursor[dst[e]], 1)] = src[e];
    }
}

// ---------------- 3. Per-node softmax + aggregation (no max pass) ----------------
__global__ void aggregate_kernel(float* __restrict__ out, int N) {
    int w = (blockIdx.x * blockDim.x + threadIdx.x) >> 5;
    int lane = threadIdx.x & 31;
    if (w >= N) return;
    int n = w;
    int base = g_off[n];
    int d = g_deg[n];

    float er0 = g_er[n * 4 + 0], er1 = g_er[n * 4 + 1];
    float er2 = g_er[n * 4 + 2], er3 = g_er[n * 4 + 3];

    // pass 1: per-edge unnormalized weights + per-head denom
    float s0 = 0.f, s1 = 0.f, s2 = 0.f, s3 = 0.f;
    for (int j = lane; j < d; j += 32) {
        int s = g_csr_src[base + j];
        float4 el4 = *reinterpret_cast<const float4*>(g_el + s * 4);
        float e0 = __expf(leaky(el4.x + er0));
        float e1 = __expf(leaky(el4.y + er1));
        float e2 = __expf(leaky(el4.z + er2));
        float e3 = __expf(leaky(el4.w + er3));
        s0 += e0; s1 += e1; s2 += e2; s3 += e3;
        g_w[base + j] = make_float4(e0, e1, e2, e3);
    }
#pragma unroll
    for (int o = 16; o > 0; o >>= 1) {
        s0 += __shfl_xor_sync(0xffffffffu, s0, o);
        s1 += __shfl_xor_sync(0xffffffffu, s1, o);
        s2 += __shfl_xor_sync(0xffffffffu, s2, o);
        s3 += __shfl_xor_sync(0xffffffffu, s3, o);
    }
    float i0 = 1.0f / fmaxf(s0, 1e-9f);
    float i1 = 1.0f / fmaxf(s1, 1e-9f);
    float i2 = 1.0f / fmaxf(s2, 1e-9f);
    float i3 = 1.0f / fmaxf(s3, 1e-9f);

    // pass 2: gather + fma; lane = output dim; prefetch next edge's s/w
    float acc0 = 0.f, acc1 = 0.f, acc2 = 0.f, acc3 = 0.f;
    if (d > 0) {
        int s = g_csr_src[base];
        float4 wv = g_w[base];
        for (int j = 0; j < d; j++) {
            int s_n = 0; float4 wv_n = make_float4(0.f, 0.f, 0.f, 0.f);
            if (j + 1 < d) {
                s_n  = g_csr_src[base + j + 1];
                wv_n = g_w[base + j + 1];
            }
            const float* f = g_feat + (size_t)s * HD;
            acc0 = fmaf(wv.x, f[0 * OUT_DIM + lane], acc0);
            acc1 = fmaf(wv.y, f[1 * OUT_DIM + lane], acc1);
            acc2 = fmaf(wv.z, f[2 * OUT_DIM + lane], acc2);
            acc3 = fmaf(wv.w, f[3 * OUT_DIM + lane], acc3);
            s = s_n; wv = wv_n;
        }
    }
    out[(size_t)n * OUT_DIM + lane] =
        0.25f * (acc0 * i0 + acc1 * i1 + acc2 * i2 + acc3 * i3);
}

// ---------------- launch ----------------
extern "C" void kernel_launch(void* const* d_in, const int* in_sizes, int n_in,
                              void* d_out, int out_size) {
    const float* x      = (const float*)d_in[0];
    const float* W      = (const float*)d_in[1];
    const float* attn_l = (const float*)d_in[2];
    const float* attn_r = (const float*)d_in[3];
    const int*   src    = (const int*)d_in[4];
    const int*   dst    = (const int*)d_in[5];
    float* out = (float*)d_out;

    int N = in_sizes[0] / IN_DIM;   // 100000
    int E = in_sizes[4];            // 1600000

    // one-time setup on the (non-captured) correctness call
    static cudaStream_t s_side = nullptr;
    static cudaEvent_t  s_fork = nullptr, s_join = nullptr;
    if (s_side == nullptr) {
        cudaStreamCreateWithFlags(&s_side, cudaStreamNonBlocking);
        cudaEventCreateWithFlags(&s_fork, cudaEventDisableTiming);
        cudaEventCreateWithFlags(&s_join, cudaEventDisableTiming);
        cudaFuncSetAttribute(gemm_tc_kernel,
                             cudaFuncAttributeMaxDynamicSharedMemorySize, SMEM_BYTES);
    }

    // 0. W split/transpose + zero degrees (fused) — main stream
    wconv_zero_kernel<<<(N + 255) / 256, 256>>>(W, N);

    // fork: CSR chain on side stream, overlapped with the GEMM
    cudaEventRecord(s_fork, 0);
    cudaStreamWaitEvent(s_side, s_fork, 0);
    {
        int nt4 = (E + 3) / 4;
        count_kernel<<<(nt4 + 255) / 256, 256, 0, s_side>>>(dst, E);
        int nb = (N + 1023) / 1024;
        scan1_kernel<<<nb, 1024, 0, s_side>>>(N);
        scan2_kernel<<<1, 128, 0, s_side>>>(nb);
        scan3_kernel<<<(N + 255) / 256, 256, 0, s_side>>>(N);
        scatter_kernel<<<(nt4 + 255) / 256, 256, 0, s_side>>>(src, dst, E);
        cudaEventRecord(s_join, s_side);
    }

    // 1. feat = x @ W on tensor cores, fused el/er epilogue — main stream
    gemm_tc_kernel<<<(N + 127) / 128, 256, SMEM_BYTES>>>(x, attn_l, attn_r, N);

    // join, then aggregate (needs both GEMM results and CSR)
    cudaStreamWaitEvent(0, s_join, 0);
    {
        int blocks = (N * 32 + 255) / 256;
        aggregate_kernel<<<blocks, 256>>>(out, N);
    }
}

// round 11
// speedup vs baseline: 1.1512x; 1.1512x over previous
#include <cuda_runtime.h>
#include <cuda_bf16.h>
#include <cuda_fp16.h>
#include <math_constants.h>

// Problem constants (shapes fixed by the dataset)
#define NODES_MAX 100000
#define EDGES_MAX 1600000
#define IN_DIM    256
#define HEADS     4
#define OUT_DIM   32
#define HD        128          // HEADS*OUT_DIM
#define NEG_SLOPE 0.2f

// ---------------- static scratch (no allocations allowed) ----------------
__device__ __half g_feath[(size_t)NODES_MAX * HD]; // [N,128] fp16 (only consumer: aggregate)
__device__ float g_el[NODES_MAX * HEADS];          // [N,4]
__device__ float g_er[NODES_MAX * HEADS];          // [N,4]
__device__ int   g_deg[NODES_MAX];
__device__ int   g_off[NODES_MAX];
__device__ int   g_cursor[NODES_MAX];
__device__ int   g_bsums[256];
__device__ int   g_csr_src[EDGES_MAX];
__device__ float4 g_w[EDGES_MAX];                  // per-edge unnormalized softmax weights
__device__ __nv_bfloat16 g_Wt_hi[HD * IN_DIM];     // W^T split: [n][k]
__device__ __nv_bfloat16 g_Wt_lo[HD * IN_DIM];

__device__ __forceinline__ float leaky(float x) {
    return x > 0.0f ? x : NEG_SLOPE * x;
}

__device__ __forceinline__ void split_bf16(float v, __nv_bfloat16& hi, __nv_bfloat16& lo) {
    hi = __float2bfloat16(v);
    lo = __float2bfloat16(v - __bfloat162float(hi));
}

// ---------------- 0. W -> transposed bf16 hi/lo split + zero degrees ----------------
__global__ void wconv_zero_kernel(const float* __restrict__ W, int N) {
    int idx = blockIdx.x * blockDim.x + threadIdx.x;
    if (idx < N) g_deg[idx] = 0;
    if (idx >= IN_DIM * HD) return;
    int k = idx >> 7;        // 0..255
    int n = idx & 127;       // 0..127
    __nv_bfloat16 hi, lo;
    split_bf16(W[idx], hi, lo);
    g_Wt_hi[n * IN_DIM + k] = hi;
    g_Wt_lo[n * IN_DIM + k] = lo;
}

// ---------------- 1. Tensor-core GEMM: feat = x @ W (+ fused el/er) ----------------
// BM=128, BN=128 (full), BK=32, 256 threads = 8 warps; warp tile 64x32.
// Software-pipelined: next chunk's global loads staged in registers during compute.
// Error-compensated: acc += Ahi*Bhi + Ahi*Blo + Alo*Bhi  (fp32 accumulate)
__device__ __forceinline__ void mma16816(float* d, const unsigned* a, const unsigned* b) {
    asm volatile(
        "mma.sync.aligned.m16n8k16.row.col.f32.bf16.bf16.f32 "
        "{%0,%1,%2,%3}, {%4,%5,%6,%7}, {%8,%9}, {%0,%1,%2,%3};\n"
        : "+f"(d[0]), "+f"(d[1]), "+f"(d[2]), "+f"(d[3])
        : "r"(a[0]), "r"(a[1]), "r"(a[2]), "r"(a[3]), "r"(b[0]), "r"(b[1]));
}

#define BK   32
#define APAD 8
#define ASTR (BK + APAD)   // 40 bf16 per row (80B) -> conflict-free frag reads

__global__ void __launch_bounds__(256, 2)
gemm_tc_kernel(const float* __restrict__ A,
               const float* __restrict__ attn_l,
               const float* __restrict__ attn_r, int M) {
    __shared__ __nv_bfloat16 As_hi[128][ASTR];
    __shared__ __nv_bfloat16 As_lo[128][ASTR];
    __shared__ __nv_bfloat16 Bs_hi[128][ASTR];   // [n][k] (B col-major)
    __shared__ __nv_bfloat16 Bs_lo[128][ASTR];

    const int tid  = threadIdx.x;
    const int wid  = tid >> 5;
    const int lane = tid & 31;
    const int brow = blockIdx.x * 128;

    const int warp_m = (wid & 1) * 64;    // 4 m-tiles of 16
    const int warp_n = (wid >> 1) * 32;   // head = wid>>1

    float acc[4][4][4];
#pragma unroll
    for (int i = 0; i < 4; i++)
#pragma unroll
        for (int j = 0; j < 4; j++)
#pragma unroll
            for (int c = 0; c < 4; c++) acc[i][j][c] = 0.0f;

    const int r  = lane >> 2;         // 0..7
    const int kq = (lane & 3) * 2;    // 0,2,4,6

    // register staging for the software pipeline
    float4 rA[4];
    uint4  rBh[2], rBl[2];

    auto ldA = [&](int chunk) {
        const int k0 = chunk * BK;
#pragma unroll
        for (int i = 0; i < 4; i++) {
            int linear = tid + 256 * i;         // 0..1023
            int row = linear >> 3;              // 0..127
            int col = (linear & 7) * 4;         // 0..28
            rA[i] = make_float4(0.f, 0.f, 0.f, 0.f);
            if (brow + row < M)
                rA[i] = *reinterpret_cast<const float4*>(A + (size_t)(brow + row) * IN_DIM + k0 + col);
        }
    };
    auto ldB = [&](int chunk) {
        const int k0 = chunk * BK;
#pragma unroll
        for (int i = 0; i < 2; i++) {
            int linear = tid + 256 * i;         // 0..511
            int n  = linear >> 2;               // 0..127
            int kk = (linear & 3) * 8;          // 0,8,16,24
            rBh[i] = *reinterpret_cast<const uint4*>(&g_Wt_hi[n * IN_DIM + k0 + kk]);
            rBl[i] = *reinterpret_cast<const uint4*>(&g_Wt_lo[n * IN_DIM + k0 + kk]);
        }
    };

    ldA(0);
    ldB(0);

    for (int chunk = 0; chunk < IN_DIM / BK; chunk++) {
        // ---- STS staged registers into smem (split A to hi/lo) ----
#pragma unroll
        for (int i = 0; i < 4; i++) {
            int linear = tid + 256 * i;
            int row = linear >> 3;
            int col = (linear & 7) * 4;
            __nv_bfloat16 h0, l0, h1, l1, h2, l2, h3, l3;
            split_bf16(rA[i].x, h0, l0); split_bf16(rA[i].y, h1, l1);
            split_bf16(rA[i].z, h2, l2); split_bf16(rA[i].w, h3, l3);
            As_hi[row][col + 0] = h0; As_hi[row][col + 1] = h1;
            As_hi[row][col + 2] = h2; As_hi[row][col + 3] = h3;
            As_lo[row][col + 0] = l0; As_lo[row][col + 1] = l1;
            As_lo[row][col + 2] = l2; As_lo[row][col + 3] = l3;
        }
#pragma unroll
        for (int i = 0; i < 2; i++) {
            int linear = tid + 256 * i;
            int n  = linear >> 2;
            int kk = (linear & 3) * 8;
            *reinterpret_cast<uint4*>(&Bs_hi[n][kk]) = rBh[i];
            *reinterpret_cast<uint4*>(&Bs_lo[n][kk]) = rBl[i];
        }
        __syncthreads();

        // ---- prefetch next chunk (LDG issues overlap the MMA work below) ----
        if (chunk < IN_DIM / BK - 1) {
            ldA(chunk + 1);
            ldB(chunk + 1);
        }

#pragma unroll
        for (int ks = 0; ks < 2; ks++) {
            const int kb = ks * 16;
            unsigned ah[4][4], al[4][4], bh[4][2], bl[4][2];
#pragma unroll
            for (int mt = 0; mt < 4; mt++) {
                int mr = warp_m + mt * 16;
                ah[mt][0] = *reinterpret_cast<const unsigned*>(&As_hi[mr + r][kb + kq]);
                ah[mt][1] = *reinterpret_cast<const unsigned*>(&As_hi[mr + r + 8][kb + kq]);
                ah[mt][2] = *reinterpret_cast<const unsigned*>(&As_hi[mr + r][kb + kq + 8]);
                ah[mt][3] = *reinterpret_cast<const unsigned*>(&As_hi[mr + r + 8][kb + kq + 8]);
                al[mt][0] = *reinterpret_cast<const unsigned*>(&As_lo[mr + r][kb + kq]);
                al[mt][1] = *reinterpret_cast<const unsigned*>(&As_lo[mr + r + 8][kb + kq]);
                al[mt][2] = *reinterpret_cast<const unsigned*>(&As_lo[mr + r][kb + kq + 8]);
                al[mt][3] = *reinterpret_cast<const unsigned*>(&As_lo[mr + r + 8][kb + kq + 8]);
            }
#pragma unroll
            for (int nt = 0; nt < 4; nt++) {
                int n = warp_n + nt * 8 + (lane >> 2);
                bh[nt][0] = *reinterpret_cast<const unsigned*>(&Bs_hi[n][kb + kq]);
                bh[nt][1] = *reinterpret_cast<const unsigned*>(&Bs_hi[n][kb + kq + 8]);
                bl[nt][0] = *reinterpret_cast<const unsigned*>(&Bs_lo[n][kb + kq]);
                bl[nt][1] = *reinterpret_cast<const unsigned*>(&Bs_lo[n][kb + kq + 8]);
            }
#pragma unroll
            for (int mt = 0; mt < 4; mt++)
#pragma unroll
                for (int nt = 0; nt < 4; nt++) {
                    mma16816(acc[mt][nt], ah[mt], bh[nt]);
                    mma16816(acc[mt][nt], ah[mt], bl[nt]);
                    mma16816(acc[mt][nt], al[mt], bh[nt]);
                }
        }
        __syncthreads();
    }

    // ---- epilogue: fp16 store to g_feath + fused el/er (warp-local head dot) ----
    const int cc = (lane & 3) * 2;
    const int head = wid >> 1;

    float alv[8], arv[8];
#pragma unroll
    for (int nt = 0; nt < 4; nt++) {
        int gcol = warp_n + nt * 8 + cc;       // global col = head*32 + local
        alv[nt * 2 + 0] = attn_l[gcol + 0];
        alv[nt * 2 + 1] = attn_l[gcol + 1];
        arv[nt * 2 + 0] = attn_r[gcol + 0];
        arv[nt * 2 + 1] = attn_r[gcol + 1];
    }

#pragma unroll
    for (int mt = 0; mt < 4; mt++) {
        float el_lo = 0.f, el_hi = 0.f, er_lo = 0.f, er_hi = 0.f;
#pragma unroll
        for (int nt = 0; nt < 4; nt++) {
            int grow = brow + warp_m + mt * 16 + r;
            int gcol = warp_n + nt * 8 + cc;
            if (grow < M)
                *reinterpret_cast<__half2*>(&g_feath[(size_t)grow * HD + gcol]) =
                    __floats2half2_rn(acc[mt][nt][0], acc[mt][nt][1]);
            if (grow + 8 < M)
                *reinterpret_cast<__half2*>(&g_feath[(size_t)(grow + 8) * HD + gcol]) =
                    __floats2half2_rn(acc[mt][nt][2], acc[mt][nt][3]);

            el_lo = fmaf(acc[mt][nt][0], alv[nt * 2], fmaf(acc[mt][nt][1], alv[nt * 2 + 1], el_lo));
            er_lo = fmaf(acc[mt][nt][0], arv[nt * 2], fmaf(acc[mt][nt][1], arv[nt * 2 + 1], er_lo));
            el_hi = fmaf(acc[mt][nt][2], alv[nt * 2], fmaf(acc[mt][nt][3], alv[nt * 2 + 1], el_hi));
            er_hi = fmaf(acc[mt][nt][2], arv[nt * 2], fmaf(acc[mt][nt][3], arv[nt * 2 + 1], er_hi));
        }
#pragma unroll
        for (int o = 1; o <= 2; o <<= 1) {
            el_lo += __shfl_xor_sync(0xffffffffu, el_lo, o);
            el_hi += __shfl_xor_sync(0xffffffffu, el_hi, o);
            er_lo += __shfl_xor_sync(0xffffffffu, er_lo, o);
            er_hi += __shfl_xor_sync(0xffffffffu, er_hi, o);
        }
        if ((lane & 3) == 0) {
            int grow = brow + warp_m + mt * 16 + r;
            if (grow < M) {
                g_el[grow * HEADS + head] = el_lo;
                g_er[grow * HEADS + head] = er_lo;
            }
            if (grow + 8 < M) {
                g_el[(grow + 8) * HEADS + head] = el_hi;
                g_er[(grow + 8) * HEADS + head] = er_hi;
            }
        }
    }
}

// ---------------- 2. CSR build ----------------
__global__ void count_kernel(const int* __restrict__ dst, int E) {
    int e4 = (blockIdx.x * blockDim.x + threadIdx.x) * 4;
    if (e4 + 3 < E) {
        int4 d4 = *reinterpret_cast<const int4*>(dst + e4);
        atomicAdd(&g_deg[d4.x], 1);
        atomicAdd(&g_deg[d4.y], 1);
        atomicAdd(&g_deg[d4.z], 1);
        atomicAdd(&g_deg[d4.w], 1);
    } else {
        for (int e = e4; e < E; e++) atomicAdd(&g_deg[dst[e]], 1);
    }
}

__global__ void scan1_kernel(int N) {
    __shared__ int sm1[1024];
    int i = blockIdx.x * 1024 + threadIdx.x;
    int v = (i < N) ? g_deg[i] : 0;
    sm1[threadIdx.x] = v;
    __syncthreads();
    for (int ofs = 1; ofs < 1024; ofs <<= 1) {
        int t = (threadIdx.x >= ofs) ? sm1[threadIdx.x - ofs] : 0;
        __syncthreads();
        sm1[threadIdx.x] += t;
        __syncthreads();
    }
    if (i < N) g_off[i] = sm1[threadIdx.x] - v;       // exclusive
    if (threadIdx.x == 1023) g_bsums[blockIdx.x] = sm1[1023];
}

// parallel block-sum scan (nb <= 128)
__global__ void scan2_kernel(int nb) {
    __shared__ int sm2[128];
    int t = threadIdx.x;
    int v = (t < nb) ? g_bsums[t] : 0;
    sm2[t] = v;
    __syncthreads();
    for (int ofs = 1; ofs < 128; ofs <<= 1) {
        int u = (t >= ofs) ? sm2[t - ofs] : 0;
        __syncthreads();
        sm2[t] += u;
        __syncthreads();
    }
    if (t < nb) g_bsums[t] = sm2[t] - v;              // exclusive
}

__global__ void scan3_kernel(int N) {
    int i = blockIdx.x * blockDim.x + threadIdx.x;
    if (i < N) {
        int o = g_off[i] + g_bsums[i >> 10];
        g_off[i] = o;
        g_cursor[i] = o;
    }
}

__global__ void scatter_kernel(const int* __restrict__ src,
                               const int* __restrict__ dst, int E) {
    int e4 = (blockIdx.x * blockDim.x + threadIdx.x) * 4;
    if (e4 + 3 < E) {
        int4 d4 = *reinterpret_cast<const int4*>(dst + e4);
        int4 s4 = *reinterpret_cast<const int4*>(src + e4);
        g_csr_src[atomicAdd(&g_cursor[d4.x], 1)] = s4.x;
        g_csr_src[atomicAdd(&g_cursor[d4.y], 1)] = s4.y;
        g_csr_src[atomicAdd(&g_cursor[d4.z], 1)] = s4.z;
        g_csr_src[atomicAdd(&g_cursor[d4.w], 1)] = s4.w;
    } else {
        for (int e = e4; e < E; e++)
            g_csr_src[atomicAdd(&g_cursor[dst[e]], 1)] = src[e];
    }
}

// ---------------- 3. Per-node softmax + aggregation ----------------
// pass 1: fp32 weights + denoms (no max pass; softmax shift-invariant, exp can't overflow fp32)
// pass 2: fp16 feat gather; lane = (dim-pair, head-pair); cross-head combine via shfl
__global__ void aggregate_kernel(float* __restrict__ out, int N) {
    int w = (blockIdx.x * blockDim.x + threadIdx.x) >> 5;
    int lane = threadIdx.x & 31;
    if (w >= N) return;
    int n = w;
    int base = g_off[n];
    int d = g_deg[n];

    float er0 = g_er[n * 4 + 0], er1 = g_er[n * 4 + 1];
    float er2 = g_er[n * 4 + 2], er3 = g_er[n * 4 + 3];

    // pass 1: per-edge unnormalized weights + per-head denom
    float s0 = 0.f, s1 = 0.f, s2 = 0.f, s3 = 0.f;
    for (int j = lane; j < d; j += 32) {
        int s = g_csr_src[base + j];
        float4 el4 = *reinterpret_cast<const float4*>(g_el + s * 4);
        float e0 = __expf(leaky(el4.x + er0));
        float e1 = __expf(leaky(el4.y + er1));
        float e2 = __expf(leaky(el4.z + er2));
        float e3 = __expf(leaky(el4.w + er3));
        s0 += e0; s1 += e1; s2 += e2; s3 += e3;
        g_w[base + j] = make_float4(e0, e1, e2, e3);
    }
#pragma unroll
    for (int o = 16; o > 0; o >>= 1) {
        s0 += __shfl_xor_sync(0xffffffffu, s0, o);
        s1 += __shfl_xor_sync(0xffffffffu, s1, o);
        s2 += __shfl_xor_sync(0xffffffffu, s2, o);
        s3 += __shfl_xor_sync(0xffffffffu, s3, o);
    }
    float i0 = 1.0f / fmaxf(s0, 1e-9f);
    float i1 = 1.0f / fmaxf(s1, 1e-9f);
    float i2 = 1.0f / fmaxf(s2, 1e-9f);
    float i3 = 1.0f / fmaxf(s3, 1e-9f);

    // pass 2: lane covers dims (m2, m2+1) of heads (hh, hh+1)
    const int m2 = (lane & 15) * 2;
    const int hh = (lane >> 4) * 2;       // 0 or 2

    float a00 = 0.f, a01 = 0.f, a10 = 0.f, a11 = 0.f;
#pragma unroll 2
    for (int j = 0; j < d; j++) {
        int s = g_csr_src[base + j];                              // broadcast
        float2 wv = *reinterpret_cast<const float2*>(
            reinterpret_cast<const float*>(&g_w[base + j]) + hh); // weights for heads hh, hh+1
        const __half* f = g_feath + (size_t)s * HD;
        float2 f0 = __half22float2(*reinterpret_cast<const __half2*>(f + hh * OUT_DIM + m2));
        float2 f1 = __half22float2(*reinterpret_cast<const __half2*>(f + (hh + 1) * OUT_DIM + m2));
        a00 = fmaf(wv.x, f0.x, a00);
        a01 = fmaf(wv.x, f0.y, a01);
        a10 = fmaf(wv.y, f1.x, a10);
        a11 = fmaf(wv.y, f1.y, a11);
    }
    float ih0 = (hh == 0) ? i0 : i2;
    float ih1 = (hh == 0) ? i1 : i3;
    float o0 = a00 * ih0 + a10 * ih1;
    float o1 = a01 * ih0 + a11 * ih1;
    o0 += __shfl_xor_sync(0xffffffffu, o0, 16);   // add other head pair
    o1 += __shfl_xor_sync(0xffffffffu, o1, 16);
    if (lane < 16)
        *reinterpret_cast<float2*>(out + (size_t)n * OUT_DIM + m2) =
            make_float2(o0 * 0.25f, o1 * 0.25f);
}

// ---------------- launch ----------------
extern "C" void kernel_launch(void* const* d_in, const int* in_sizes, int n_in,
                              void* d_out, int out_size) {
    const float* x      = (const float*)d_in[0];
    const float* W      = (const float*)d_in[1];
    const float* attn_l = (const float*)d_in[2];
    const float* attn_r = (const float*)d_in[3];
    const int*   src    = (const int*)d_in[4];
    const int*   dst    = (const int*)d_in[5];
    float* out = (float*)d_out;

    int N = in_sizes[0] / IN_DIM;   // 100000
    int E = in_sizes[4];            // 1600000

    // lazily create side stream + events ONCE (on the non-captured correctness
    // call); reused on the capture call via the documented fork/join pattern.
    static cudaStream_t s_side = nullptr;
    static cudaEvent_t  s_fork = nullptr, s_join = nullptr;
    if (s_side == nullptr) {
        cudaStreamCreateWithFlags(&s_side, cudaStreamNonBlocking);
        cudaEventCreateWithFlags(&s_fork, cudaEventDisableTiming);
        cudaEventCreateWithFlags(&s_join, cudaEventDisableTiming);
    }

    // 0. W split/transpose + zero degrees (fused) — main stream
    wconv_zero_kernel<<<(N + 255) / 256, 256>>>(W, N);

    // fork: CSR chain on side stream, overlapped with the GEMM
    cudaEventRecord(s_fork, 0);
    cudaStreamWaitEvent(s_side, s_fork, 0);
    {
        int nt4 = (E + 3) / 4;
        count_kernel<<<(nt4 + 255) / 256, 256, 0, s_side>>>(dst, E);
        int nb = (N + 1023) / 1024;
        scan1_kernel<<<nb, 1024, 0, s_side>>>(N);
        scan2_kernel<<<1, 128, 0, s_side>>>(nb);
        scan3_kernel<<<(N + 255) / 256, 256, 0, s_side>>>(N);
        scatter_kernel<<<(nt4 + 255) / 256, 256, 0, s_side>>>(src, dst, E);
        cudaEventRecord(s_join, s_side);
    }

    // 1. feat = x @ W on tensor cores, fused el/er epilogue — main stream
    gemm_tc_kernel<<<(N + 127) / 128, 256>>>(x, attn_l, attn_r, N);

    // join, then aggregate (needs both GEMM results and CSR)
    cudaStreamWaitEvent(0, s_join, 0);
    {
        int blocks = (N * 32 + 255) / 256;
        aggregate_kernel<<<blocks, 256>>>(out, N);
    }
}

// round 13
// speedup vs baseline: 1.4484x; 1.2582x over previous
#include <cuda_runtime.h>
#include <cuda_fp16.h>
#include <math_constants.h>

// Problem constants (shapes fixed by the dataset)
#define NODES_MAX 100000
#define EDGES_MAX 1600000
#define IN_DIM    256
#define HEADS     4
#define OUT_DIM   32
#define HD        128          // HEADS*OUT_DIM
#define NEG_SLOPE 0.2f

// ---------------- static scratch (no allocations allowed) ----------------
__device__ __half g_feath[(size_t)NODES_MAX * HD]; // [N,128] fp16 (only consumer: aggregate)
__device__ float g_el[NODES_MAX * HEADS];          // [N,4]
__device__ float g_er[NODES_MAX * HEADS];          // [N,4]
__device__ int   g_deg[NODES_MAX];
__device__ int   g_off[NODES_MAX];
__device__ int   g_cursor[NODES_MAX];
__device__ int   g_bsums[256];
__device__ int   g_csr_src[EDGES_MAX];
__device__ float4 g_w[EDGES_MAX];                  // per-edge unnormalized softmax weights
__device__ __half g_Wt_h[HD * IN_DIM];             // W^T fp16: [n][k]

__device__ __forceinline__ float leaky(float x) {
    return x > 0.0f ? x : NEG_SLOPE * x;
}

__device__ __forceinline__ unsigned cvta_smem(const void* p) {
    unsigned a;
    asm("{ .reg .u64 t; cvta.to.shared.u64 t, %1; cvt.u32.u64 %0, t; }" : "=r"(a) : "l"(p));
    return a;
}

__device__ __forceinline__ void ldsm_x4(unsigned& r0, unsigned& r1, unsigned& r2, unsigned& r3,
                                        unsigned addr) {
    asm volatile("ldmatrix.sync.aligned.m8n8.x4.shared.b16 {%0,%1,%2,%3}, [%4];"
                 : "=r"(r0), "=r"(r1), "=r"(r2), "=r"(r3) : "r"(addr));
}
__device__ __forceinline__ void ldsm_x2(unsigned& r0, unsigned& r1, unsigned addr) {
    asm volatile("ldmatrix.sync.aligned.m8n8.x2.shared.b16 {%0,%1}, [%2];"
                 : "=r"(r0), "=r"(r1) : "r"(addr));
}

// ---------------- 0. W -> transposed fp16 + zero degrees ----------------
__global__ void wconv_zero_kernel(const float* __restrict__ W, int N) {
    int idx = blockIdx.x * blockDim.x + threadIdx.x;
    if (idx < N) g_deg[idx] = 0;
    if (idx >= IN_DIM * HD) return;
    int k = idx >> 7;        // 0..255
    int n = idx & 127;       // 0..127
    g_Wt_h[n * IN_DIM + k] = __float2half_rn(W[idx]);
}

// ---------------- 1. Tensor-core GEMM: feat = x @ W (+ fused el/er) ----------------
// BM=128, BN=128, BK=32, 256 threads = 8 warps; warp tile 64x32 (warp cols = one head).
// Single-pass fp16 MMA with fp32 accumulate; ldmatrix fragment loads;
// register-staged prefetch of the next chunk (round-7 pipeline shape).
__device__ __forceinline__ void mma16816(float* d, const unsigned* a, const unsigned* b) {
    asm volatile(
        "mma.sync.aligned.m16n8k16.row.col.f32.f16.f16.f32 "
        "{%0,%1,%2,%3}, {%4,%5,%6,%7}, {%8,%9}, {%0,%1,%2,%3};\n"
        : "+f"(d[0]), "+f"(d[1]), "+f"(d[2]), "+f"(d[3])
        : "r"(a[0]), "r"(a[1]), "r"(a[2]), "r"(a[3]), "r"(b[0]), "r"(b[1]));
}

#define BK   32
#define APAD 8
#define ASTR (BK + APAD)   // 40 fp16 per row (80B): LDSM 8-row pattern conflict-free

__global__ void __launch_bounds__(256, 2)
gemm_tc_kernel(const float* __restrict__ A,
               const float* __restrict__ attn_l,
               const float* __restrict__ attn_r, int M) {
    __shared__ __half As[128][ASTR];
    __shared__ __half Bs[128][ASTR];   // [n][k] (B col-major)

    const int tid  = threadIdx.x;
    const int wid  = tid >> 5;
    const int lane = tid & 31;
    const int brow = blockIdx.x * 128;

    const int warp_m = (wid & 1) * 64;    // 4 m-tiles of 16
    const int warp_n = (wid >> 1) * 32;   // head = wid>>1

    float acc[4][4][4];
#pragma unroll
    for (int i = 0; i < 4; i++)
#pragma unroll
        for (int j = 0; j < 4; j++)
#pragma unroll
            for (int c = 0; c < 4; c++) acc[i][j][c] = 0.0f;

    // ldmatrix per-lane address components
    const unsigned as_base = cvta_smem(&As[0][0]);
    const unsigned bs_base = cvta_smem(&Bs[0][0]);
    const int a_row = warp_m + (lane & 15);
    const int a_col = (lane >> 4) * 8;
    const int b_row = warp_n + (lane & 7);
    const int b_col = ((lane >> 3) & 1) * 8;

    // register staging for the software pipeline
    float4 rA[4];
    uint4  rB[2];

    auto ldA = [&](int chunk) {
        const int k0 = chunk * BK;
#pragma unroll
        for (int i = 0; i < 4; i++) {
            int linear = tid + 256 * i;         // 0..1023
            int row = linear >> 3;              // 0..127
            int col = (linear & 7) * 4;         // 0..28
            rA[i] = make_float4(0.f, 0.f, 0.f, 0.f);
            if (brow + row < M)
                rA[i] = *reinterpret_cast<const float4*>(A + (size_t)(brow + row) * IN_DIM + k0 + col);
        }
    };
    auto ldB = [&](int chunk) {
        const int k0 = chunk * BK;
#pragma unroll
        for (int i = 0; i < 2; i++) {
            int linear = tid + 256 * i;         // 0..511
            int n  = linear >> 2;               // 0..127
            int kk = (linear & 3) * 8;          // 0,8,16,24
            rB[i] = *reinterpret_cast<const uint4*>(&g_Wt_h[n * IN_DIM + k0 + kk]);
        }
    };

    ldA(0);
    ldB(0);

    for (int chunk = 0; chunk < IN_DIM / BK; chunk++) {
        // ---- STS staged registers into smem (fp16 convert for A) ----
#pragma unroll
        for (int i = 0; i < 4; i++) {
            int linear = tid + 256 * i;
            int row = linear >> 3;
            int col = (linear & 7) * 4;
            __half2 h01 = __floats2half2_rn(rA[i].x, rA[i].y);
            __half2 h23 = __floats2half2_rn(rA[i].z, rA[i].w);
            uint2 u;
            u.x = reinterpret_cast<unsigned&>(h01);
            u.y = reinterpret_cast<unsigned&>(h23);
            *reinterpret_cast<uint2*>(&As[row][col]) = u;
        }
#pragma unroll
        for (int i = 0; i < 2; i++) {
            int linear = tid + 256 * i;
            int n  = linear >> 2;
            int kk = (linear & 3) * 8;
            *reinterpret_cast<uint4*>(&Bs[n][kk]) = rB[i];
        }
        __syncthreads();

        // ---- prefetch next chunk (LDG issues overlap the MMA work below) ----
        if (chunk < IN_DIM / BK - 1) {
            ldA(chunk + 1);
            ldB(chunk + 1);
        }

#pragma unroll
        for (int ks = 0; ks < 2; ks++) {
            const int kb = ks * 16;
            unsigned b[4][2];
#pragma unroll
            for (int nt = 0; nt < 4; nt++)
                ldsm_x2(b[nt][0], b[nt][1],
                        bs_base + ((b_row + nt * 8) * ASTR + kb + b_col) * 2);
#pragma unroll
            for (int mt = 0; mt < 4; mt++) {
                unsigned a[4];
                ldsm_x4(a[0], a[1], a[2], a[3],
                        as_base + ((a_row + mt * 16) * ASTR + kb + a_col) * 2);
#pragma unroll
                for (int nt = 0; nt < 4; nt++)
                    mma16816(acc[mt][nt], a, b[nt]);
            }
        }
        __syncthreads();
    }

    // ---- epilogue: fp16 store to g_feath + fused el/er (warp-local head dot) ----
    const int r  = lane >> 2;         // 0..7
    const int cc = (lane & 3) * 2;
    const int head = wid >> 1;

    float alv[8], arv[8];
#pragma unroll
    for (int nt = 0; nt < 4; nt++) {
        int gcol = warp_n + nt * 8 + cc;       // global col = head*32 + local
        alv[nt * 2 + 0] = attn_l[gcol + 0];
        alv[nt * 2 + 1] = attn_l[gcol + 1];
        arv[nt * 2 + 0] = attn_r[gcol + 0];
        arv[nt * 2 + 1] = attn_r[gcol + 1];
    }

#pragma unroll
    for (int mt = 0; mt < 4; mt++) {
        float el_lo = 0.f, el_hi = 0.f, er_lo = 0.f, er_hi = 0.f;
#pragma unroll
        for (int nt = 0; nt < 4; nt++) {
            int grow = brow + warp_m + mt * 16 + r;
            int gcol = warp_n + nt * 8 + cc;
            if (grow < M)
                *reinterpret_cast<__half2*>(&g_feath[(size_t)grow * HD + gcol]) =
                    __floats2half2_rn(acc[mt][nt][0], acc[mt][nt][1]);
            if (grow + 8 < M)
                *reinterpret_cast<__half2*>(&g_feath[(size_t)(grow + 8) * HD + gcol]) =
                    __floats2half2_rn(acc[mt][nt][2], acc[mt][nt][3]);

            el_lo = fmaf(acc[mt][nt][0], alv[nt * 2], fmaf(acc[mt][nt][1], alv[nt * 2 + 1], el_lo));
            er_lo = fmaf(acc[mt][nt][0], arv[nt * 2], fmaf(acc[mt][nt][1], arv[nt * 2 + 1], er_lo));
            el_hi = fmaf(acc[mt][nt][2], alv[nt * 2], fmaf(acc[mt][nt][3], alv[nt * 2 + 1], el_hi));
            er_hi = fmaf(acc[mt][nt][2], arv[nt * 2], fmaf(acc[mt][nt][3], arv[nt * 2 + 1], er_hi));
        }
#pragma unroll
        for (int o = 1; o <= 2; o <<= 1) {
            el_lo += __shfl_xor_sync(0xffffffffu, el_lo, o);
            el_hi += __shfl_xor_sync(0xffffffffu, el_hi, o);
            er_lo += __shfl_xor_sync(0xffffffffu, er_lo, o);
            er_hi += __shfl_xor_sync(0xffffffffu, er_hi, o);
        }
        if ((lane & 3) == 0) {
            int grow = brow + warp_m + mt * 16 + r;
            if (grow < M) {
                g_el[grow * HEADS + head] = el_lo;
                g_er[grow * HEADS + head] = er_lo;
            }
            if (grow + 8 < M) {
                g_el[(grow + 8) * HEADS + head] = el_hi;
                g_er[(grow + 8) * HEADS + head] = er_hi;
            }
        }
    }
}

// ---------------- 2. CSR build ----------------
__global__ void count_kernel(const int* __restrict__ dst, int E) {
    int e4 = (blockIdx.x * blockDim.x + threadIdx.x) * 4;
    if (e4 + 3 < E) {
        int4 d4 = *reinterpret_cast<const int4*>(dst + e4);
        atomicAdd(&g_deg[d4.x], 1);
        atomicAdd(&g_deg[d4.y], 1);
        atomicAdd(&g_deg[d4.z], 1);
        atomicAdd(&g_deg[d4.w], 1);
    } else {
        for (int e = e4; e < E; e++) atomicAdd(&g_deg[dst[e]], 1);
    }
}

__global__ void scan1_kernel(int N) {
    __shared__ int sm1[1024];
    int i = blockIdx.x * 1024 + threadIdx.x;
    int v = (i < N) ? g_deg[i] : 0;
    sm1[threadIdx.x] = v;
    __syncthreads();
    for (int ofs = 1; ofs < 1024; ofs <<= 1) {
        int t = (threadIdx.x >= ofs) ? sm1[threadIdx.x - ofs] : 0;
        __syncthreads();
        sm1[threadIdx.x] += t;
        __syncthreads();
    }
    if (i < N) g_off[i] = sm1[threadIdx.x] - v;       // exclusive
    if (threadIdx.x == 1023) g_bsums[blockIdx.x] = sm1[1023];
}

// parallel block-sum scan (nb <= 128)
__global__ void scan2_kernel(int nb) {
    __shared__ int sm2[128];
    int t = threadIdx.x;
    int v = (t < nb) ? g_bsums[t] : 0;
    sm2[t] = v;
    __syncthreads();
    for (int ofs = 1; ofs < 128; ofs <<= 1) {
        int u = (t >= ofs) ? sm2[t - ofs] : 0;
        __syncthreads();
        sm2[t] += u;
        __syncthreads();
    }
    if (t < nb) g_bsums[t] = sm2[t] - v;              // exclusive
}

__global__ void scan3_kernel(int N) {
    int i = blockIdx.x * blockDim.x + threadIdx.x;
    if (i < N) {
        int o = g_off[i] + g_bsums[i >> 10];
        g_off[i] = o;
        g_cursor[i] = o;
    }
}

__global__ void scatter_kernel(const int* __restrict__ src,
                               const int* __restrict__ dst, int E) {
    int e4 = (blockIdx.x * blockDim.x + threadIdx.x) * 4;
    if (e4 + 3 < E) {
        int4 d4 = *reinterpret_cast<const int4*>(dst + e4);
        int4 s4 = *reinterpret_cast<const int4*>(src + e4);
        g_csr_src[atomicAdd(&g_cursor[d4.x], 1)] = s4.x;
        g_csr_src[atomicAdd(&g_cursor[d4.y], 1)] = s4.y;
        g_csr_src[atomicAdd(&g_cursor[d4.z], 1)] = s4.z;
        g_csr_src[atomicAdd(&g_cursor[d4.w], 1)] = s4.w;
    } else {
        for (int e = e4; e < E; e++)
            g_csr_src[atomicAdd(&g_cursor[dst[e]], 1)] = src[e];
    }
}

// ---------------- 3. Per-node softmax + aggregation ----------------
// pass 1: fp32 weights + denoms (no max pass; softmax shift-invariant, exp can't overflow fp32)
// pass 2: fp16 feat gather; lane = (dim-pair, head-pair); cross-head combine via shfl
__global__ void aggregate_kernel(float* __restrict__ out, int N) {
    int w = (blockIdx.x * blockDim.x + threadIdx.x) >> 5;
    int lane = threadIdx.x & 31;
    if (w >= N) return;
    int n = w;
    int base = g_off[n];
    int d = g_deg[n];

    float er0 = g_er[n * 4 + 0], er1 = g_er[n * 4 + 1];
    float er2 = g_er[n * 4 + 2], er3 = g_er[n * 4 + 3];

    // pass 1: per-edge unnormalized weights + per-head denom
    float s0 = 0.f, s1 = 0.f, s2 = 0.f, s3 = 0.f;
    for (int j = lane; j < d; j += 32) {
        int s = g_csr_src[base + j];
        float4 el4 = *reinterpret_cast<const float4*>(g_el + s * 4);
        float e0 = __expf(leaky(el4.x + er0));
        float e1 = __expf(leaky(el4.y + er1));
        float e2 = __expf(leaky(el4.z + er2));
        float e3 = __expf(leaky(el4.w + er3));
        s0 += e0; s1 += e1; s2 += e2; s3 += e3;
        g_w[base + j] = make_float4(e0, e1, e2, e3);
    }
#pragma unroll
    for (int o = 16; o > 0; o >>= 1) {
        s0 += __shfl_xor_sync(0xffffffffu, s0, o);
        s1 += __shfl_xor_sync(0xffffffffu, s1, o);
        s2 += __shfl_xor_sync(0xffffffffu, s2, o);
        s3 += __shfl_xor_sync(0xffffffffu, s3, o);
    }
    float i0 = 1.0f / fmaxf(s0, 1e-9f);
    float i1 = 1.0f / fmaxf(s1, 1e-9f);
    float i2 = 1.0f / fmaxf(s2, 1e-9f);
    float i3 = 1.0f / fmaxf(s3, 1e-9f);

    // pass 2: lane covers dims (m2, m2+1) of heads (hh, hh+1)
    const int m2 = (lane & 15) * 2;
    const int hh = (lane >> 4) * 2;       // 0 or 2

    float a00 = 0.f, a01 = 0.f, a10 = 0.f, a11 = 0.f;
#pragma unroll 2
    for (int j = 0; j < d; j++) {
        int s = g_csr_src[base + j];                              // broadcast
        float2 wv = *reinterpret_cast<const float2*>(
            reinterpret_cast<const float*>(&g_w[base + j]) + hh); // weights for heads hh, hh+1
        const __half* f = g_feath + (size_t)s * HD;
        float2 f0 = __half22float2(*reinterpret_cast<const __half2*>(f + hh * OUT_DIM + m2));
        float2 f1 = __half22float2(*reinterpret_cast<const __half2*>(f + (hh + 1) * OUT_DIM + m2));
        a00 = fmaf(wv.x, f0.x, a00);
        a01 = fmaf(wv.x, f0.y, a01);
        a10 = fmaf(wv.y, f1.x, a10);
        a11 = fmaf(wv.y, f1.y, a11);
    }
    float ih0 = (hh == 0) ? i0 : i2;
    float ih1 = (hh == 0) ? i1 : i3;
    float o0 = a00 * ih0 + a10 * ih1;
    float o1 = a01 * ih0 + a11 * ih1;
    o0 += __shfl_xor_sync(0xffffffffu, o0, 16);   // add other head pair
    o1 += __shfl_xor_sync(0xffffffffu, o1, 16);
    if (lane < 16)
        *reinterpret_cast<float2*>(out + (size_t)n * OUT_DIM + m2) =
            make_float2(o0 * 0.25f, o1 * 0.25f);
}

// ---------------- launch ----------------
extern "C" void kernel_launch(void* const* d_in, const int* in_sizes, int n_in,
                              void* d_out, int out_size) {
    const float* x      = (const float*)d_in[0];
    const float* W      = (const float*)d_in[1];
    const float* attn_l = (const float*)d_in[2];
    const float* attn_r = (const float*)d_in[3];
    const int*   src    = (const int*)d_in[4];
    const int*   dst    = (const int*)d_in[5];
    float* out = (float*)d_out;

    int N = in_sizes[0] / IN_DIM;   // 100000
    int E = in_sizes[4];            // 1600000

    // lazily create side stream + events ONCE (on the non-captured correctness
    // call); reused on the capture call via the documented fork/join pattern.
    static cudaStream_t s_side = nullptr;
    static cudaEvent_t  s_fork = nullptr, s_join = nullptr;
    if (s_side == nullptr) {
        cudaStreamCreateWithFlags(&s_side, cudaStreamNonBlocking);
        cudaEventCreateWithFlags(&s_fork, cudaEventDisableTiming);
        cudaEventCreateWithFlags(&s_join, cudaEventDisableTiming);
    }

    // 0. W transpose/convert + zero degrees (fused) — main stream
    wconv_zero_kernel<<<(N + 255) / 256, 256>>>(W, N);

    // fork: CSR chain on side stream, overlapped with the GEMM
    cudaEventRecord(s_fork, 0);
    cudaStreamWaitEvent(s_side, s_fork, 0);
    {
        int nt4 = (E + 3) / 4;
        count_kernel<<<(nt4 + 255) / 256, 256, 0, s_side>>>(dst, E);
        int nb = (N + 1023) / 1024;
        scan1_kernel<<<nb, 1024, 0, s_side>>>(N);
        scan2_kernel<<<1, 128, 0, s_side>>>(nb);
        scan3_kernel<<<(N + 255) / 256, 256, 0, s_side>>>(N);
        scatter_kernel<<<(nt4 + 255) / 256, 256, 0, s_side>>>(src, dst, E);
        cudaEventRecord(s_join, s_side);
    }

    // 1. feat = x @ W on tensor cores, fused el/er epilogue — main stream
    gemm_tc_kernel<<<(N + 127) / 128, 256>>>(x, attn_l, attn_r, N);

    // join, then aggregate (needs both GEMM results and CSR)
    cudaStreamWaitEvent(0, s_join, 0);
    {
        int blocks = (N * 32 + 255) / 256;
        aggregate_kernel<<<blocks, 256>>>(out, N);
    }
}

// round 14
// speedup vs baseline: 1.4503x; 1.0013x over previous
#include <cuda_runtime.h>
#include <cuda_fp16.h>
#include <math_constants.h>

// Problem constants (shapes fixed by the dataset)
#define NODES_MAX 100000
#define EDGES_MAX 1600000
#define IN_DIM    256
#define HEADS     4
#define OUT_DIM   32
#define HD        128          // HEADS*OUT_DIM
#define NEG_SLOPE 0.2f

// ---------------- static scratch (no allocations allowed) ----------------
__device__ __half g_feath[(size_t)NODES_MAX * HD]; // [N,128] fp16 (only consumer: aggregate)
__device__ float g_el[NODES_MAX * HEADS];          // [N,4]
__device__ float g_er[NODES_MAX * HEADS];          // [N,4]
__device__ int   g_deg[NODES_MAX];
__device__ int   g_off[NODES_MAX];
__device__ int   g_cursor[NODES_MAX];
__device__ int   g_bsums[256];
__device__ int   g_csr_src[EDGES_MAX];
__device__ __half g_wh[(size_t)EDGES_MAX * HEADS]; // per-edge unnormalized weights, fp16
__device__ __half g_Wt_h[HD * IN_DIM];             // W^T fp16: [n][k]

__device__ __forceinline__ float leaky(float x) {
    return x > 0.0f ? x : NEG_SLOPE * x;
}

__device__ __forceinline__ unsigned cvta_smem(const void* p) {
    unsigned a;
    asm("{ .reg .u64 t; cvta.to.shared.u64 t, %1; cvt.u32.u64 %0, t; }" : "=r"(a) : "l"(p));
    return a;
}

__device__ __forceinline__ void ldsm_x4(unsigned& r0, unsigned& r1, unsigned& r2, unsigned& r3,
                                        unsigned addr) {
    asm volatile("ldmatrix.sync.aligned.m8n8.x4.shared.b16 {%0,%1,%2,%3}, [%4];"
                 : "=r"(r0), "=r"(r1), "=r"(r2), "=r"(r3) : "r"(addr));
}
__device__ __forceinline__ void ldsm_x2(unsigned& r0, unsigned& r1, unsigned addr) {
    asm volatile("ldmatrix.sync.aligned.m8n8.x2.shared.b16 {%0,%1}, [%2];"
                 : "=r"(r0), "=r"(r1) : "r"(addr));
}

// ---------------- 0. W -> transposed fp16 + zero degrees ----------------
__global__ void wconv_zero_kernel(const float* __restrict__ W, int N) {
    int idx = blockIdx.x * blockDim.x + threadIdx.x;
    if (idx < N) g_deg[idx] = 0;
    if (idx >= IN_DIM * HD) return;
    int k = idx >> 7;        // 0..255
    int n = idx & 127;       // 0..127
    g_Wt_h[n * IN_DIM + k] = __float2half_rn(W[idx]);
}

// ---------------- 1. Tensor-core GEMM: feat = x @ W (+ fused el/er) ----------------
// BM=128, BN=128, BK=32, 256 threads = 8 warps; warp tile 64x32 (warp cols = one head).
// Single-pass fp16 MMA with fp32 accumulate; ldmatrix fragment loads;
// register-staged prefetch of the next chunk.
__device__ __forceinline__ void mma16816(float* d, const unsigned* a, const unsigned* b) {
    asm volatile(
        "mma.sync.aligned.m16n8k16.row.col.f32.f16.f16.f32 "
        "{%0,%1,%2,%3}, {%4,%5,%6,%7}, {%8,%9}, {%0,%1,%2,%3};\n"
        : "+f"(d[0]), "+f"(d[1]), "+f"(d[2]), "+f"(d[3])
        : "r"(a[0]), "r"(a[1]), "r"(a[2]), "r"(a[3]), "r"(b[0]), "r"(b[1]));
}

#define BK   32
#define APAD 8
#define ASTR (BK + APAD)   // 40 fp16 per row (80B): LDSM 8-row pattern conflict-free

__global__ void __launch_bounds__(256, 2)
gemm_tc_kernel(const float* __restrict__ A,
               const float* __restrict__ attn_l,
               const float* __restrict__ attn_r, int M) {
    __shared__ __half As[128][ASTR];
    __shared__ __half Bs[128][ASTR];   // [n][k] (B col-major)

    const int tid  = threadIdx.x;
    const int wid  = tid >> 5;
    const int lane = tid & 31;
    const int brow = blockIdx.x * 128;

    const int warp_m = (wid & 1) * 64;    // 4 m-tiles of 16
    const int warp_n = (wid >> 1) * 32;   // head = wid>>1

    float acc[4][4][4];
#pragma unroll
    for (int i = 0; i < 4; i++)
#pragma unroll
        for (int j = 0; j < 4; j++)
#pragma unroll
            for (int c = 0; c < 4; c++) acc[i][j][c] = 0.0f;

    // ldmatrix per-lane address components
    const unsigned as_base = cvta_smem(&As[0][0]);
    const unsigned bs_base = cvta_smem(&Bs[0][0]);
    const int a_row = warp_m + (lane & 15);
    const int a_col = (lane >> 4) * 8;
    const int b_row = warp_n + (lane & 7);
    const int b_col = ((lane >> 3) & 1) * 8;

    // register staging for the software pipeline
    float4 rA[4];
    uint4  rB[2];

    auto ldA = [&](int chunk) {
        const int k0 = chunk * BK;
#pragma unroll
        for (int i = 0; i < 4; i++) {
            int linear = tid + 256 * i;         // 0..1023
            int row = linear >> 3;              // 0..127
            int col = (linear & 7) * 4;         // 0..28
            rA[i] = make_float4(0.f, 0.f, 0.f, 0.f);
            if (brow + row < M)
                rA[i] = *reinterpret_cast<const float4*>(A + (size_t)(brow + row) * IN_DIM + k0 + col);
        }
    };
    auto ldB = [&](int chunk) {
        const int k0 = chunk * BK;
#pragma unroll
        for (int i = 0; i < 2; i++) {
            int linear = tid + 256 * i;         // 0..511
            int n  = linear >> 2;               // 0..127
            int kk = (linear & 3) * 8;          // 0,8,16,24
            rB[i] = *reinterpret_cast<const uint4*>(&g_Wt_h[n * IN_DIM + k0 + kk]);
        }
    };

    ldA(0);
    ldB(0);

    for (int chunk = 0; chunk < IN_DIM / BK; chunk++) {
        // ---- STS staged registers into smem (fp16 convert for A) ----
#pragma unroll
        for (int i = 0; i < 4; i++) {
            int linear = tid + 256 * i;
            int row = linear >> 3;
            int col = (linear & 7) * 4;
            __half2 h01 = __floats2half2_rn(rA[i].x, rA[i].y);
            __half2 h23 = __floats2half2_rn(rA[i].z, rA[i].w);
            uint2 u;
            u.x = reinterpret_cast<unsigned&>(h01);
            u.y = reinterpret_cast<unsigned&>(h23);
            *reinterpret_cast<uint2*>(&As[row][col]) = u;
        }
#pragma unroll
        for (int i = 0; i < 2; i++) {
            int linear = tid + 256 * i;
            int n  = linear >> 2;
            int kk = (linear & 3) * 8;
            *reinterpret_cast<uint4*>(&Bs[n][kk]) = rB[i];
        }
        __syncthreads();

        // ---- prefetch next chunk (LDG issues overlap the MMA work below) ----
        if (chunk < IN_DIM / BK - 1) {
            ldA(chunk + 1);
            ldB(chunk + 1);
        }

#pragma unroll
        for (int ks = 0; ks < 2; ks++) {
            const int kb = ks * 16;
            unsigned b[4][2];
#pragma unroll
            for (int nt = 0; nt < 4; nt++)
                ldsm_x2(b[nt][0], b[nt][1],
                        bs_base + ((b_row + nt * 8) * ASTR + kb + b_col) * 2);
#pragma unroll
            for (int mt = 0; mt < 4; mt++) {
                unsigned a[4];
                ldsm_x4(a[0], a[1], a[2], a[3],
                        as_base + ((a_row + mt * 16) * ASTR + kb + a_col) * 2);
#pragma unroll
                for (int nt = 0; nt < 4; nt++)
                    mma16816(acc[mt][nt], a, b[nt]);
            }
        }
        __syncthreads();
    }

    // ---- epilogue: fp16 store to g_feath + fused el/er (warp-local head dot) ----
    const int r  = lane >> 2;         // 0..7
    const int cc = (lane & 3) * 2;
    const int head = wid >> 1;

    float alv[8], arv[8];
#pragma unroll
    for (int nt = 0; nt < 4; nt++) {
        int gcol = warp_n + nt * 8 + cc;       // global col = head*32 + local
        alv[nt * 2 + 0] = attn_l[gcol + 0];
        alv[nt * 2 + 1] = attn_l[gcol + 1];
        arv[nt * 2 + 0] = attn_r[gcol + 0];
        arv[nt * 2 + 1] = attn_r[gcol + 1];
    }

#pragma unroll
    for (int mt = 0; mt < 4; mt++) {
        float el_lo = 0.f, el_hi = 0.f, er_lo = 0.f, er_hi = 0.f;
#pragma unroll
        for (int nt = 0; nt < 4; nt++) {
            int grow = brow + warp_m + mt * 16 + r;
            int gcol = warp_n + nt * 8 + cc;
            if (grow < M)
                *reinterpret_cast<__half2*>(&g_feath[(size_t)grow * HD + gcol]) =
                    __floats2half2_rn(acc[mt][nt][0], acc[mt][nt][1]);
            if (grow + 8 < M)
                *reinterpret_cast<__half2*>(&g_feath[(size_t)(grow + 8) * HD + gcol]) =
                    __floats2half2_rn(acc[mt][nt][2], acc[mt][nt][3]);

            el_lo = fmaf(acc[mt][nt][0], alv[nt * 2], fmaf(acc[mt][nt][1], alv[nt * 2 + 1], el_lo));
            er_lo = fmaf(acc[mt][nt][0], arv[nt * 2], fmaf(acc[mt][nt][1], arv[nt * 2 + 1], er_lo));
            el_hi = fmaf(acc[mt][nt][2], alv[nt * 2], fmaf(acc[mt][nt][3], alv[nt * 2 + 1], el_hi));
            er_hi = fmaf(acc[mt][nt][2], arv[nt * 2], fmaf(acc[mt][nt][3], arv[nt * 2 + 1], er_hi));
        }
#pragma unroll
        for (int o = 1; o <= 2; o <<= 1) {
            el_lo += __shfl_xor_sync(0xffffffffu, el_lo, o);
            el_hi += __shfl_xor_sync(0xffffffffu, el_hi, o);
            er_lo += __shfl_xor_sync(0xffffffffu, er_lo, o);
            er_hi += __shfl_xor_sync(0xffffffffu, er_hi, o);
        }
        if ((lane & 3) == 0) {
            int grow = brow + warp_m + mt * 16 + r;
            if (grow < M) {
                g_el[grow * HEADS + head] = el_lo;
                g_er[grow * HEADS + head] = er_lo;
            }
            if (grow + 8 < M) {
                g_el[(grow + 8) * HEADS + head] = el_hi;
                g_er[(grow + 8) * HEADS + head] = er_hi;
            }
        }
    }
}

// ---------------- 2. CSR build ----------------
__global__ void count_kernel(const int* __restrict__ dst, int E) {
    int e4 = (blockIdx.x * blockDim.x + threadIdx.x) * 4;
    if (e4 + 3 < E) {
        int4 d4 = *reinterpret_cast<const int4*>(dst + e4);
        atomicAdd(&g_deg[d4.x], 1);
        atomicAdd(&g_deg[d4.y], 1);
        atomicAdd(&g_deg[d4.z], 1);
        atomicAdd(&g_deg[d4.w], 1);
    } else {
        for (int e = e4; e < E; e++) atomicAdd(&g_deg[dst[e]], 1);
    }
}

__global__ void scan1_kernel(int N) {
    __shared__ int sm1[1024];
    int i = blockIdx.x * 1024 + threadIdx.x;
    int v = (i < N) ? g_deg[i] : 0;
    sm1[threadIdx.x] = v;
    __syncthreads();
    for (int ofs = 1; ofs < 1024; ofs <<= 1) {
        int t = (threadIdx.x >= ofs) ? sm1[threadIdx.x - ofs] : 0;
        __syncthreads();
        sm1[threadIdx.x] += t;
        __syncthreads();
    }
    if (i < N) g_off[i] = sm1[threadIdx.x] - v;       // exclusive
    if (threadIdx.x == 1023) g_bsums[blockIdx.x] = sm1[1023];
}

// parallel block-sum scan (nb <= 128)
__global__ void scan2_kernel(int nb) {
    __shared__ int sm2[128];
    int t = threadIdx.x;
    int v = (t < nb) ? g_bsums[t] : 0;
    sm2[t] = v;
    __syncthreads();
    for (int ofs = 1; ofs < 128; ofs <<= 1) {
        int u = (t >= ofs) ? sm2[t - ofs] : 0;
        __syncthreads();
        sm2[t] += u;
        __syncthreads();
    }
    if (t < nb) g_bsums[t] = sm2[t] - v;              // exclusive
}

__global__ void scan3_kernel(int N) {
    int i = blockIdx.x * blockDim.x + threadIdx.x;
    if (i < N) {
        int o = g_off[i] + g_bsums[i >> 10];
        g_off[i] = o;
        g_cursor[i] = o;
    }
}

__global__ void scatter_kernel(const int* __restrict__ src,
                               const int* __restrict__ dst, int E) {
    int e4 = (blockIdx.x * blockDim.x + threadIdx.x) * 4;
    if (e4 + 3 < E) {
        int4 d4 = *reinterpret_cast<const int4*>(dst + e4);
        int4 s4 = *reinterpret_cast<const int4*>(src + e4);
        g_csr_src[atomicAdd(&g_cursor[d4.x], 1)] = s4.x;
        g_csr_src[atomicAdd(&g_cursor[d4.y], 1)] = s4.y;
        g_csr_src[atomicAdd(&g_cursor[d4.z], 1)] = s4.z;
        g_csr_src[atomicAdd(&g_cursor[d4.w], 1)] = s4.w;
    } else {
        for (int e = e4; e < E; e++)
            g_csr_src[atomicAdd(&g_cursor[dst[e]], 1)] = src[e];
    }
}

// ---------------- 3. Per-node softmax + aggregation ----------------
// pass 1: fp32 denoms, store fp16 half4 weights (no max pass; softmax shift-invariant)
// pass 2: lane = (head, dim-quad); per edge: 1 csr + 1 weight + 1 half4 feat LDG
__global__ void aggregate_kernel(float* __restrict__ out, int N) {
    int w = (blockIdx.x * blockDim.x + threadIdx.x) >> 5;
    int lane = threadIdx.x & 31;
    if (w >= N) return;
    int n = w;
    int base = g_off[n];
    int d = g_deg[n];

    float er0 = g_er[n * 4 + 0], er1 = g_er[n * 4 + 1];
    float er2 = g_er[n * 4 + 2], er3 = g_er[n * 4 + 3];

    // pass 1: per-edge unnormalized weights (fp16 store) + per-head fp32 denom
    float s0 = 0.f, s1 = 0.f, s2 = 0.f, s3 = 0.f;
    for (int j = lane; j < d; j += 32) {
        int s = g_csr_src[base + j];
        float4 el4 = *reinterpret_cast<const float4*>(g_el + s * 4);
        float e0 = __expf(leaky(el4.x + er0));
        float e1 = __expf(leaky(el4.y + er1));
        float e2 = __expf(leaky(el4.z + er2));
        float e3 = __expf(leaky(el4.w + er3));
        s0 += e0; s1 += e1; s2 += e2; s3 += e3;
        __half2 h01 = __floats2half2_rn(e0, e1);
        __half2 h23 = __floats2half2_rn(e2, e3);
        uint2 u;
        u.x = reinterpret_cast<unsigned&>(h01);
        u.y = reinterpret_cast<unsigned&>(h23);
        *reinterpret_cast<uint2*>(&g_wh[(size_t)(base + j) * 4]) = u;
    }
#pragma unroll
    for (int o = 16; o > 0; o >>= 1) {
        s0 += __shfl_xor_sync(0xffffffffu, s0, o);
        s1 += __shfl_xor_sync(0xffffffffu, s1, o);
        s2 += __shfl_xor_sync(0xffffffffu, s2, o);
        s3 += __shfl_xor_sync(0xffffffffu, s3, o);
    }
    float i0 = 1.0f / fmaxf(s0, 1e-9f);
    float i1 = 1.0f / fmaxf(s1, 1e-9f);
    float i2 = 1.0f / fmaxf(s2, 1e-9f);
    float i3 = 1.0f / fmaxf(s3, 1e-9f);

    // pass 2: lane covers head (lane>>3) and dims m4..m4+3 (m4 = 4*(lane&7))
    const int head = lane >> 3;           // 0..3
    const int m4 = (lane & 7) * 4;        // 0..28

    float a0 = 0.f, a1 = 0.f, a2 = 0.f, a3 = 0.f;
#pragma unroll 2
    for (int j = 0; j < d; j++) {
        int s = g_csr_src[base + j];                              // broadcast
        float wv = __half2float(g_wh[(size_t)(base + j) * 4 + head]);
        const __half* f = g_feath + (size_t)s * HD + head * OUT_DIM + m4;
        uint2 u = *reinterpret_cast<const uint2*>(f);             // 4 halves
        __half2 f01 = reinterpret_cast<__half2&>(u.x);
        __half2 f23 = reinterpret_cast<__half2&>(u.y);
        float2 F0 = __half22float2(f01);
        float2 F1 = __half22float2(f23);
        a0 = fmaf(wv, F0.x, a0);
        a1 = fmaf(wv, F0.y, a1);
        a2 = fmaf(wv, F1.x, a2);
        a3 = fmaf(wv, F1.y, a3);
    }
    float ih = (head == 0) ? i0 : (head == 1) ? i1 : (head == 2) ? i2 : i3;
    a0 *= ih; a1 *= ih; a2 *= ih; a3 *= ih;
    // sum the 4 heads: lanes {q, q+8, q+16, q+24} hold the same dim-quad
#pragma unroll
    for (int o = 8; o <= 16; o <<= 1) {
        a0 += __shfl_xor_sync(0xffffffffu, a0, o);
        a1 += __shfl_xor_sync(0xffffffffu, a1, o);
        a2 += __shfl_xor_sync(0xffffffffu, a2, o);
        a3 += __shfl_xor_sync(0xffffffffu, a3, o);
    }
    if (lane < 8)
        *reinterpret_cast<float4*>(out + (size_t)n * OUT_DIM + m4) =
            make_float4(a0 * 0.25f, a1 * 0.25f, a2 * 0.25f, a3 * 0.25f);
}

// ---------------- launch ----------------
extern "C" void kernel_launch(void* const* d_in, const int* in_sizes, int n_in,
                              void* d_out, int out_size) {
    const float* x      = (const float*)d_in[0];
    const float* W      = (const float*)d_in[1];
    const float* attn_l = (const float*)d_in[2];
    const float* attn_r = (const float*)d_in[3];
    const int*   src    = (const int*)d_in[4];
    const int*   dst    = (const int*)d_in[5];
    float* out = (float*)d_out;

    int N = in_sizes[0] / IN_DIM;   // 100000
    int E = in_sizes[4];            // 1600000

    // lazily create side stream + events ONCE (on the non-captured correctness
    // call); reused on the capture call via the documented fork/join pattern.
    static cudaStream_t s_side = nullptr;
    static cudaEvent_t  s_fork = nullptr, s_join = nullptr;
    if (s_side == nullptr) {
        cudaStreamCreateWithFlags(&s_side, cudaStreamNonBlocking);
        cudaEventCreateWithFlags(&s_fork, cudaEventDisableTiming);
        cudaEventCreateWithFlags(&s_join, cudaEventDisableTiming);
    }

    // 0. W transpose/convert + zero degrees (fused) — main stream
    wconv_zero_kernel<<<(N + 255) / 256, 256>>>(W, N);

    // fork: CSR chain on side stream, overlapped with the GEMM
    cudaEventRecord(s_fork, 0);
    cudaStreamWaitEvent(s_side, s_fork, 0);
    {
        int nt4 = (E + 3) / 4;
        count_kernel<<<(nt4 + 255) / 256, 256, 0, s_side>>>(dst, E);
        int nb = (N + 1023) / 1024;
        scan1_kernel<<<nb, 1024, 0, s_side>>>(N);
        scan2_kernel<<<1, 128, 0, s_side>>>(nb);
        scan3_kernel<<<(N + 255) / 256, 256, 0, s_side>>>(N);
        scatter_kernel<<<(nt4 + 255) / 256, 256, 0, s_side>>>(src, dst, E);
        cudaEventRecord(s_join, s_side);
    }

    // 1. feat = x @ W on tensor cores, fused el/er epilogue — main stream
    gemm_tc_kernel<<<(N + 127) / 128, 256>>>(x, attn_l, attn_r, N);

    // join, then aggregate (needs both GEMM results and CSR)
    cudaStreamWaitEvent(0, s_join, 0);
    {
        int blocks = (N * 32 + 255) / 256;
        aggregate_kernel<<<blocks, 256>>>(out, N);
    }
}